// round 6
// baseline (speedup 1.0000x reference)
#include <cuda_runtime.h>
#include <cuda_bf16.h>
#include <stdint.h>

// ---------------- problem constants ----------------
#define N_SPANS 1024
#define DIM     512
#define HID     150
#define WIN     250
#define OUTW    (WIN + 1)
#define HPAD    160
#define NTHREADS 512

// row strides (bytes) for bf16 tiles (multiples of 16 for ldmatrix)
#define RS1 144        // layer-1 A and all B chunks: 64 bf16 + pad
#define RS2 336        // layer-2 A (h1): 160 bf16 + pad
#define BCHUNK_BYTES (HPAD * RS1)   // 23040 per split per chunk
#define BCHUNK_V16   (BCHUNK_BYTES / 16)  // 1440

// ---------------- smem layout (bytes) ----------------
#define OFF_JROW 0
#define OFF_SMJ  512
#define OFF_GIS  1024
#define OFF_GIAS 3072
#define OFF_B2S  3712
#define OFF_W3S  4352
#define OFF_SRED 4992               // 4 x 128 floats
#define OFF_A_HI 7168               // 128 x RS1
#define OFF_A_LO (OFF_A_HI + 128*RS1)
#define OFF_B_HI (OFF_A_LO + 128*RS1)
#define OFF_B_LO (OFF_B_HI + BCHUNK_BYTES)
#define OFF_GJ   (OFF_B_LO + BCHUNK_BYTES)     // 128 x 608
#define OFF_A2_HI OFF_GJ                        // aliases gjt (write after sync)
#define OFF_A2_LO (OFF_A2_HI + 128*RS2)
#define SMEM_TOTAL (OFF_A2_LO + 128*RS2)        // 176128

// ---------------- device scratch ----------------
__device__ float d_gia[N_SPANS * HID];          // g@W1a + b1
__device__ float d_gjt[N_SPANS * 152];          // g@W1b, padded rows
__device__ unsigned char d_w1t_hi[8 * BCHUNK_BYTES];
__device__ unsigned char d_w1t_lo[8 * BCHUNK_BYTES];
__device__ unsigned char d_w2t_hi[3 * BCHUNK_BYTES];
__device__ unsigned char d_w2t_lo[3 * BCHUNK_BYTES];

// ---------------- helpers ----------------
__device__ __forceinline__ uint32_t smem_u32(const void* p) {
    uint32_t a;
    asm("{ .reg .u64 t; cvta.to.shared.u64 t, %1; cvt.u32.u64 %0, t; }" : "=r"(a) : "l"(p));
    return a;
}
__device__ __forceinline__ uint32_t packbf2(float a, float b) {
    __nv_bfloat162 t;
    t.x = __float2bfloat16(a);
    t.y = __float2bfloat16(b);
    return *reinterpret_cast<uint32_t*>(&t);
}
__device__ __forceinline__ uint32_t split2(float a, float b, float& ra, float& rb) {
    __nv_bfloat16 ha = __float2bfloat16(a), hb = __float2bfloat16(b);
    ra = a - __bfloat162float(ha);
    rb = b - __bfloat162float(hb);
    __nv_bfloat162 t; t.x = ha; t.y = hb;
    return *reinterpret_cast<uint32_t*>(&t);
}
__device__ __forceinline__ void mma16816(float* c, const uint32_t* a,
                                         uint32_t b0, uint32_t b1) {
    asm volatile(
        "mma.sync.aligned.m16n8k16.row.col.f32.bf16.bf16.f32 "
        "{%0,%1,%2,%3}, {%4,%5,%6,%7}, {%8,%9}, {%0,%1,%2,%3};"
        : "+f"(c[0]), "+f"(c[1]), "+f"(c[2]), "+f"(c[3])
        : "r"(a[0]), "r"(a[1]), "r"(a[2]), "r"(a[3]), "r"(b0), "r"(b1));
}
__device__ __forceinline__ void ldsm_x4(uint32_t* r, uint32_t addr) {
    asm volatile("ldmatrix.sync.aligned.m8n8.x4.shared.b16 {%0,%1,%2,%3}, [%4];"
        : "=r"(r[0]), "=r"(r[1]), "=r"(r[2]), "=r"(r[3]) : "r"(addr));
}
__device__ __forceinline__ void ldsm_x2(uint32_t* r, uint32_t addr) {
    asm volatile("ldmatrix.sync.aligned.m8n8.x2.shared.b16 {%0,%1}, [%2];"
        : "=r"(r[0]), "=r"(r[1]) : "r"(addr));
}
#define CPA16(dst, src) asm volatile("cp.async.ca.shared.global [%0], [%1], 16;" :: "r"(dst), "l"(src))
#define CPA_COMMIT()    asm volatile("cp.async.commit_group;" ::: "memory")
#define CPA_WAIT0()     asm volatile("cp.async.wait_group 0;" ::: "memory")

// ---------------------------------------------------------------------------
// prep_kernel: blocks [0,128) = gia/gjt GEMM; blocks [128,568) = weight split.
//
// GEMM part: C = G @ [W1a|W1b] (+b1 for the gia half).
//   block tile 32 rows x 80 cols, 256 threads, micro 2x5, K chunks of 64.
//   blockIdx: mt = b>>2 (row tile), ct = b&3 (col tile over 320-col space;
//   cols [0,160)=gia half, [160,320)=gjt half, valid col<150 within half).
// ---------------------------------------------------------------------------
__global__ __launch_bounds__(256)
void prep_kernel(const float* __restrict__ g,
                 const float* __restrict__ W1,
                 const float* __restrict__ b1,
                 const float* __restrict__ W2) {
    const int tid = threadIdx.x;
    if (blockIdx.x < 128) {
        __shared__ float gs[32][64];
        __shared__ float Ws[64][80];
        const int mt = blockIdx.x >> 2, ct = blockIdx.x & 3;
        const int half = ct >> 1, ncol = (ct & 1) * 80;
        const int tx = tid & 15, ty = tid >> 4;

        float acc[2][5];
#pragma unroll
        for (int a = 0; a < 2; a++)
#pragma unroll
            for (int j = 0; j < 5; j++) acc[a][j] = 0.f;

        for (int kc = 0; kc < 8; kc++) {
#pragma unroll
            for (int r = 0; r < 8; r++) {
                const int ix = tid + r * 256, rr = ix >> 6, kk = ix & 63;
                gs[rr][kk] = g[(size_t)(mt * 32 + rr) * DIM + kc * 64 + kk];
            }
#pragma unroll
            for (int r = 0; r < 20; r++) {
                const int ix = tid + r * 256, kk = ix / 80, nn = ix % 80;
                const int col = ncol + nn;
                Ws[kk][nn] = (col < HID)
                    ? W1[(size_t)(half * DIM + kc * 64 + kk) * HID + col] : 0.f;
            }
            __syncthreads();
#pragma unroll 4
            for (int k = 0; k < 64; k++) {
                const float a0 = gs[ty * 2][k], a1 = gs[ty * 2 + 1][k];
#pragma unroll
                for (int j = 0; j < 5; j++) {
                    const float w = Ws[k][tx + 16 * j];
                    acc[0][j] += a0 * w;
                    acc[1][j] += a1 * w;
                }
            }
            __syncthreads();
        }
#pragma unroll
        for (int rr = 0; rr < 2; rr++) {
            const int row = mt * 32 + ty * 2 + rr;
#pragma unroll
            for (int j = 0; j < 5; j++) {
                const int col = ncol + tx + 16 * j;
                if (col < HID) {
                    if (!half) d_gia[row * HID + col] = acc[rr][j] + b1[col];
                    else       d_gjt[row * 152 + col] = acc[rr][j];
                }
            }
        }
        if (ct == 3 && tid < 64)
            d_gjt[(mt * 32 + (tid >> 1)) * 152 + HID + (tid & 1)] = 0.f;
        return;
    }

    // ---- weight split part ----
    const int idx = (blockIdx.x - 128) * 256 + tid;
    const int NW1 = 8 * HPAD * 64;
    if (idx < NW1) {
        const int c = idx / (HPAD * 64), r = idx % (HPAD * 64), n = r / 64, k = r % 64;
        const int d = c * 64 + k;
        const float v = (n < HID) ? W1[(size_t)(2 * DIM + d) * HID + n] : 0.f;
        __nv_bfloat16 hi = __float2bfloat16(v);
        __nv_bfloat16 lo = __float2bfloat16(v - __bfloat162float(hi));
        const uint32_t off = c * BCHUNK_BYTES + n * RS1 + k * 2;
        *(__nv_bfloat16*)(d_w1t_hi + off) = hi;
        *(__nv_bfloat16*)(d_w1t_lo + off) = lo;
    } else if (idx < NW1 + 3 * HPAD * 64) {
        const int i2 = idx - NW1;
        const int c = i2 / (HPAD * 64), r = i2 % (HPAD * 64), n = r / 64, k = r % 64;
        const int kk = c * 64 + k;
        const float v = (n < HID && kk < HID) ? W2[(size_t)kk * HID + n] : 0.f;
        __nv_bfloat16 hi = __float2bfloat16(v);
        __nv_bfloat16 lo = __float2bfloat16(v - __bfloat162float(hi));
        const uint32_t off = c * BCHUNK_BYTES + n * RS1 + k * 2;
        *(__nv_bfloat16*)(d_w2t_hi + off) = hi;
        *(__nv_bfloat16*)(d_w2t_lo + off) = lo;
    }
}

// ---------------------------------------------------------------------------
// Main pair MLP. CTA = (span i, 128 window rows). 512 threads, 16 warps 4Mx4N,
// warp tile 32(M) x 40(N). ldmatrix + cp.async + gj register prefetch.
// ---------------------------------------------------------------------------
__global__ __launch_bounds__(NTHREADS, 1)
void pair_mma_kernel(const float* __restrict__ g,
                     const float* __restrict__ sm,
                     const float* __restrict__ b2,
                     const float* __restrict__ W3,
                     const float* __restrict__ b3,
                     float* __restrict__ out) {
    extern __shared__ unsigned char smem[];
    const uint32_t sbase = smem_u32(smem);
    const int tid  = threadIdx.x;
    const int wid  = tid >> 5, lane = tid & 31;
    const int g8   = lane >> 2, tig = lane & 3;
    const int wm   = wid & 3, wn = wid >> 2;
    const int i    = blockIdx.y;
    const int k0   = blockIdx.x * 128;

    int*   jrow = (int*)(smem + OFF_JROW);
    float* smjf = (float*)(smem + OFF_SMJ);
    float* gis  = (float*)(smem + OFF_GIS);
    float* gias = (float*)(smem + OFF_GIAS);
    float* b2s  = (float*)(smem + OFF_B2S);
    float* w3s  = (float*)(smem + OFF_W3S);
    float* sred = (float*)(smem + OFF_SRED);

    // ---- init ----
    if (tid < DIM) gis[tid] = g[(size_t)i * DIM + tid];
    if (tid < HPAD) {
        const bool v = tid < HID;
        gias[tid] = v ? d_gia[i * HID + tid] : 0.f;
        b2s[tid]  = v ? b2[tid] : 0.f;
        w3s[tid]  = v ? W3[tid] : 0.f;
    }
    if (tid < 128) {
        const int k = k0 + tid;
        int j = i - WIN + k;
        int jc = j < 0 ? 0 : (j > N_SPANS - 1 ? N_SPANS - 1 : j);
        jrow[tid] = jc;
        smjf[tid] = sm[jc];
    }
    __syncthreads();

    // ---- stage gjt tile (consumed after layer-1; overlaps compute) ----
    {
        const int m = tid >> 2, q = tid & 3;
        const uint4* src = (const uint4*)(d_gjt + jrow[m] * 152);
        uint4* dst = (uint4*)(smem + OFF_GJ + m * 608);
#pragma unroll
        for (int r = 0; r < 10; r++) {
            const int ix = q * 10 + r;
            if (ix < 38) dst[ix] = src[ix];
        }
    }

    float acc[2][5][4];
#pragma unroll
    for (int a = 0; a < 2; a++)
#pragma unroll
        for (int b = 0; b < 5; b++)
#pragma unroll
            for (int e = 0; e < 4; e++) acc[a][b][e] = 0.f;

    const int bm  = tid >> 2;           // build row
    const int bq  = (tid & 3) * 16;     // build k-offset (floats)
    const int jcm = jrow[bm];
    const int rowA = wm * 32 + g8;      // fragment base A row

    // ldmatrix lane addresses
    const uint32_t aAddrH  = sbase + OFF_A_HI + (wm * 32 + (lane & 15)) * RS1 + ((lane >> 4) << 4);
    const uint32_t aAddrL  = aAddrH + (OFF_A_LO - OFF_A_HI);
    const uint32_t a2AddrH = sbase + OFF_A2_HI + (wm * 32 + (lane & 15)) * RS2 + ((lane >> 4) << 4);
    const uint32_t a2AddrL = a2AddrH + (OFF_A2_LO - OFF_A2_HI);
    const uint32_t bAddrH  = sbase + OFF_B_HI +
        (wn * 40 + (lane & 7) + ((lane >> 4) << 3)) * RS1 + (((lane >> 3) & 1) << 4);
    const uint32_t bAddrL  = bAddrH + BCHUNK_BYTES;
    const uint32_t bAddr2H = sbase + OFF_B_HI +
        (wn * 40 + 32 + (lane & 7)) * RS1 + (((lane >> 3) & 1) << 4);
    const uint32_t bAddr2L = bAddr2H + BCHUNK_BYTES;

    // prefetch gj chunk 0 (16 floats per thread)
    float4 pgj[4];
    {
        const float4* gj4 = (const float4*)(g + (size_t)jcm * DIM + bq);
#pragma unroll
        for (int v = 0; v < 4; v++) pgj[v] = gj4[v];
    }

    // ================= layer 1: K=512, 8 chunks of 64 =================
    for (int c = 0; c < 8; c++) {
        if (c) __syncthreads();   // prior mma done before overwriting A/B
        // issue B chunk copy (cp.async)
        {
            const unsigned char* sh = d_w1t_hi + c * BCHUNK_BYTES;
            const unsigned char* sl = d_w1t_lo + c * BCHUNK_BYTES;
#pragma unroll
            for (int r = 0; r < 3; r++) {
                const int ix = tid + r * NTHREADS;
                if (ix < BCHUNK_V16) {
                    CPA16(sbase + OFF_B_HI + ix * 16, sh + ix * 16);
                    CPA16(sbase + OFF_B_LO + ix * 16, sl + ix * 16);
                }
            }
            CPA_COMMIT();
        }
        // build A chunk from prefetched regs
        {
            const float4* gi4 = (const float4*)(gis + c * 64 + bq);
            unsigned char* ah = smem + OFF_A_HI + bm * RS1 + bq * 2;
            unsigned char* al = smem + OFF_A_LO + bm * RS1 + bq * 2;
#pragma unroll
            for (int v = 0; v < 4; v++) {
                const float4 a4 = pgj[v], i4 = gi4[v];
                float p0 = a4.x * i4.x, p1 = a4.y * i4.y;
                float p2 = a4.z * i4.z, p3 = a4.w * i4.w;
                float r0, r1, r2, r3;
                uint2 uh, ul;
                uh.x = split2(p0, p1, r0, r1);
                uh.y = split2(p2, p3, r2, r3);
                ul.x = packbf2(r0, r1);
                ul.y = packbf2(r2, r3);
                *(uint2*)(ah + v * 8) = uh;
                *(uint2*)(al + v * 8) = ul;
            }
        }
        // prefetch next gj chunk (completes under the mma below)
        if (c < 7) {
            const float4* gj4 = (const float4*)(g + (size_t)jcm * DIM + (c + 1) * 64 + bq);
#pragma unroll
            for (int v = 0; v < 4; v++) pgj[v] = gj4[v];
        }
        CPA_WAIT0();
        __syncthreads();

        // mma over 4 k16 steps
#pragma unroll
        for (int ks = 0; ks < 4; ks++) {
            const uint32_t ko = ks * 32;
            uint32_t Ah0[4], Ah1[4], Al0[4], Al1[4];
            ldsm_x4(Ah0, aAddrH + ko);
            ldsm_x4(Ah1, aAddrH + 16 * RS1 + ko);
            ldsm_x4(Al0, aAddrL + ko);
            ldsm_x4(Al1, aAddrL + 16 * RS1 + ko);
#pragma unroll
            for (int p2 = 0; p2 < 2; p2++) {
                uint32_t BH[4], BL[4];
                ldsm_x4(BH, bAddrH + p2 * 16 * RS1 + ko);
                ldsm_x4(BL, bAddrL + p2 * 16 * RS1 + ko);
                const int nA = 2 * p2, nB = 2 * p2 + 1;
                mma16816(acc[0][nA], Ah0, BH[0], BH[1]);
                mma16816(acc[1][nA], Ah1, BH[0], BH[1]);
                mma16816(acc[0][nA], Al0, BH[0], BH[1]);
                mma16816(acc[1][nA], Al1, BH[0], BH[1]);
                mma16816(acc[0][nA], Ah0, BL[0], BL[1]);
                mma16816(acc[1][nA], Ah1, BL[0], BL[1]);
                mma16816(acc[0][nB], Ah0, BH[2], BH[3]);
                mma16816(acc[1][nB], Ah1, BH[2], BH[3]);
                mma16816(acc[0][nB], Al0, BH[2], BH[3]);
                mma16816(acc[1][nB], Al1, BH[2], BH[3]);
                mma16816(acc[0][nB], Ah0, BL[2], BL[3]);
                mma16816(acc[1][nB], Ah1, BL[2], BL[3]);
            }
            {
                uint32_t BH[2], BL[2];
                ldsm_x2(BH, bAddr2H + ko);
                ldsm_x2(BL, bAddr2L + ko);
                mma16816(acc[0][4], Ah0, BH[0], BH[1]);
                mma16816(acc[1][4], Ah1, BH[0], BH[1]);
                mma16816(acc[0][4], Al0, BH[0], BH[1]);
                mma16816(acc[1][4], Al1, BH[0], BH[1]);
                mma16816(acc[0][4], Ah0, BL[0], BL[1]);
                mma16816(acc[1][4], Ah1, BL[0], BL[1]);
            }
        }
    }

    // ---- layer-1 epilogue: h1 = relu(acc + gia + gjt) (in registers) ----
#pragma unroll
    for (int mf = 0; mf < 2; mf++) {
        const int r = rowA + mf * 16;
#pragma unroll
        for (int nf = 0; nf < 5; nf++) {
            const int n0 = wn * 40 + nf * 8 + tig * 2;
            if (n0 < HID) {
                const float2 ga = *(const float2*)(gias + n0);
                const float2 gj0 = *(const float2*)(smem + OFF_GJ + r * 608 + n0 * 4);
                const float2 gj1 = *(const float2*)(smem + OFF_GJ + (r + 8) * 608 + n0 * 4);
                acc[mf][nf][0] = fmaxf(acc[mf][nf][0] + gj0.x + ga.x, 0.f);
                acc[mf][nf][1] = fmaxf(acc[mf][nf][1] + gj0.y + ga.y, 0.f);
                acc[mf][nf][2] = fmaxf(acc[mf][nf][2] + gj1.x + ga.x, 0.f);
                acc[mf][nf][3] = fmaxf(acc[mf][nf][3] + gj1.y + ga.y, 0.f);
            } else {
                acc[mf][nf][0] = acc[mf][nf][1] = acc[mf][nf][2] = acc[mf][nf][3] = 0.f;
            }
        }
    }
    __syncthreads();   // all gjt reads done before A2 overwrites that region

    // ---- write h1 split tiles into A2 ----
#pragma unroll
    for (int mf = 0; mf < 2; mf++) {
        const int r = rowA + mf * 16;
#pragma unroll
        for (int nf = 0; nf < 5; nf++) {
            const int n0 = wn * 40 + nf * 8 + tig * 2;
            float r0, r1;
            uint32_t h = split2(acc[mf][nf][0], acc[mf][nf][1], r0, r1);
            *(uint32_t*)(smem + OFF_A2_HI + r * RS2 + n0 * 2) = h;
            *(uint32_t*)(smem + OFF_A2_LO + r * RS2 + n0 * 2) = packbf2(r0, r1);
            h = split2(acc[mf][nf][2], acc[mf][nf][3], r0, r1);
            *(uint32_t*)(smem + OFF_A2_HI + (r + 8) * RS2 + n0 * 2) = h;
            *(uint32_t*)(smem + OFF_A2_LO + (r + 8) * RS2 + n0 * 2) = packbf2(r0, r1);
        }
    }

#pragma unroll
    for (int a = 0; a < 2; a++)
#pragma unroll
        for (int b = 0; b < 5; b++)
#pragma unroll
            for (int e = 0; e < 4; e++) acc[a][b][e] = 0.f;

    // ================= layer 2: K=160 (3 chunks: 64,64,32) =================
    for (int c2 = 0; c2 < 3; c2++) {
        __syncthreads();   // A2 writes (c2==0) / prior mma B reads done
        {
            const unsigned char* sh = d_w2t_hi + c2 * BCHUNK_BYTES;
            const unsigned char* sl = d_w2t_lo + c2 * BCHUNK_BYTES;
#pragma unroll
            for (int r = 0; r < 3; r++) {
                const int ix = tid + r * NTHREADS;
                if (ix < BCHUNK_V16) {
                    CPA16(sbase + OFF_B_HI + ix * 16, sh + ix * 16);
                    CPA16(sbase + OFF_B_LO + ix * 16, sl + ix * 16);
                }
            }
            CPA_COMMIT();
            CPA_WAIT0();
        }
        __syncthreads();
        const int nks = (c2 < 2) ? 4 : 2;
        for (int ks = 0; ks < nks; ks++) {
            const uint32_t ko  = ks * 32;
            const uint32_t ko2 = c2 * 128 + ks * 32;
            uint32_t Ah0[4], Ah1[4], Al0[4], Al1[4];
            ldsm_x4(Ah0, a2AddrH + ko2);
            ldsm_x4(Ah1, a2AddrH + 16 * RS2 + ko2);
            ldsm_x4(Al0, a2AddrL + ko2);
            ldsm_x4(Al1, a2AddrL + 16 * RS2 + ko2);
#pragma unroll
            for (int p2 = 0; p2 < 2; p2++) {
                uint32_t BH[4], BL[4];
                ldsm_x4(BH, bAddrH + p2 * 16 * RS1 + ko);
                ldsm_x4(BL, bAddrL + p2 * 16 * RS1 + ko);
                const int nA = 2 * p2, nB = 2 * p2 + 1;
                mma16816(acc[0][nA], Ah0, BH[0], BH[1]);
                mma16816(acc[1][nA], Ah1, BH[0], BH[1]);
                mma16816(acc[0][nA], Al0, BH[0], BH[1]);
                mma16816(acc[1][nA], Al1, BH[0], BH[1]);
                mma16816(acc[0][nA], Ah0, BL[0], BL[1]);
                mma16816(acc[1][nA], Ah1, BL[0], BL[1]);
                mma16816(acc[0][nB], Ah0, BH[2], BH[3]);
                mma16816(acc[1][nB], Ah1, BH[2], BH[3]);
                mma16816(acc[0][nB], Al0, BH[2], BH[3]);
                mma16816(acc[1][nB], Al1, BH[2], BH[3]);
                mma16816(acc[0][nB], Ah0, BL[2], BL[3]);
                mma16816(acc[1][nB], Ah1, BL[2], BL[3]);
            }
            {
                uint32_t BH[2], BL[2];
                ldsm_x2(BH, bAddr2H + ko);
                ldsm_x2(BL, bAddr2L + ko);
                mma16816(acc[0][4], Ah0, BH[0], BH[1]);
                mma16816(acc[1][4], Ah1, BH[0], BH[1]);
                mma16816(acc[0][4], Al0, BH[0], BH[1]);
                mma16816(acc[1][4], Al1, BH[0], BH[1]);
                mma16816(acc[0][4], Ah0, BL[0], BL[1]);
                mma16816(acc[1][4], Ah1, BL[0], BL[1]);
            }
        }
    }

    // ---- final: s = relu(acc2 + b2) . W3, quad-shuffle reduce ----
#pragma unroll
    for (int mf = 0; mf < 2; mf++) {
        float pr = 0.f, pr8 = 0.f;
#pragma unroll
        for (int nf = 0; nf < 5; nf++) {
            const int n0 = wn * 40 + nf * 8 + tig * 2;
            const float2 bb = *(const float2*)(b2s + n0);
            const float2 ww = *(const float2*)(w3s + n0);
            pr  += fmaxf(acc[mf][nf][0] + bb.x, 0.f) * ww.x
                 + fmaxf(acc[mf][nf][1] + bb.y, 0.f) * ww.y;
            pr8 += fmaxf(acc[mf][nf][2] + bb.x, 0.f) * ww.x
                 + fmaxf(acc[mf][nf][3] + bb.y, 0.f) * ww.y;
        }
        pr  += __shfl_xor_sync(0xffffffffu, pr, 1);
        pr  += __shfl_xor_sync(0xffffffffu, pr, 2);
        pr8 += __shfl_xor_sync(0xffffffffu, pr8, 1);
        pr8 += __shfl_xor_sync(0xffffffffu, pr8, 2);
        if (tig == 0) {
            sred[wn * 128 + rowA + mf * 16]     = pr;
            sred[wn * 128 + rowA + mf * 16 + 8] = pr8;
        }
    }
    __syncthreads();

    if (tid < 128) {
        const float s = sred[tid] + sred[128 + tid] + sred[256 + tid] + sred[384 + tid];
        const int k = k0 + tid;
        if (k < WIN) {
            const int j = i - WIN + k;
            out[i * OUTW + k] = (j >= 0) ? (sm[i] + smjf[tid] + s + b3[0]) : 0.f;
        } else if (k == WIN) {
            out[i * OUTW + k] = 0.f;  // trailing epsilon column
        }
    }
}

// ---------------------------------------------------------------------------
extern "C" void kernel_launch(void* const* d_in, const int* in_sizes, int n_in,
                              void* d_out, int out_size) {
    const float* g  = (const float*)d_in[0];
    const float* sm = (const float*)d_in[1];
    const float* W1 = (const float*)d_in[2];
    const float* b1 = (const float*)d_in[3];
    const float* W2 = (const float*)d_in[4];
    const float* b2 = (const float*)d_in[5];
    const float* W3 = (const float*)d_in[6];
    const float* b3 = (const float*)d_in[7];
    float* out = (float*)d_out;

    cudaFuncSetAttribute(pair_mma_kernel, cudaFuncAttributeMaxDynamicSharedMemorySize,
                         SMEM_TOTAL);

    // 128 GEMM blocks + 440 weight-split blocks (11*160*64/256)
    prep_kernel<<<128 + 440, 256>>>(g, W1, b1, W2);
    pair_mma_kernel<<<dim3(2, N_SPANS), NTHREADS, SMEM_TOTAL>>>(g, sm, b2, W3, b3, out);
}

// round 10
// speedup vs baseline: 1.0037x; 1.0037x over previous
#include <cuda_runtime.h>
#include <cuda_bf16.h>
#include <stdint.h>

// ---------------- problem constants ----------------
#define N_SPANS 1024
#define DIM     512
#define HID     150
#define WIN     250
#define OUTW    (WIN + 1)
#define HPAD    160
#define NTHREADS 256
#define MTILE   64

// row strides (bytes) for bf16 tiles (multiples of 16 for ldmatrix)
#define RS1 144        // layer-1 A and all B chunks: 64 bf16 + pad
#define RS2 336        // layer-2 A (h1): 160 bf16 + pad
#define BCHUNK_BYTES (HPAD * RS1)   // 23040 per split per chunk
#define BCHUNK_V16   (BCHUNK_BYTES / 16)  // 1440

// ---------------- smem layout (bytes) ----------------
#define OFF_JROW 0                  // 64 ints
#define OFF_SMJ  256                // 64 floats
#define OFF_GIS  512                // 512 floats
#define OFF_GIAS 2560               // 160 floats
#define OFF_B2S  3200               // 160 floats
#define OFF_W3S  3840               // 160 floats
#define OFF_SRED 4480               // 4 x 64 floats
#define OFF_A_HI 5504               // 64 x RS1
#define OFF_A_LO (OFF_A_HI + MTILE*RS1)
#define OFF_B_HI (OFF_A_LO + MTILE*RS1)
#define OFF_B_LO (OFF_B_HI + BCHUNK_BYTES)
#define OFF_GJ   (OFF_B_LO + BCHUNK_BYTES)     // 64 x 608 (aliased under A2)
#define OFF_A2_HI OFF_GJ                        // 64 x RS2
#define OFF_A2_LO (OFF_A2_HI + MTILE*RS2)
#define SMEM_TOTAL (OFF_A2_LO + MTILE*RS2)      // 113024 -> 2 CTAs/SM

// ---------------- device scratch ----------------
__device__ float d_gia[N_SPANS * HID];          // g@W1a + b1
__device__ float d_gjt[N_SPANS * 152];          // g@W1b, padded rows
__device__ unsigned char d_w1t_hi[8 * BCHUNK_BYTES];
__device__ unsigned char d_w1t_lo[8 * BCHUNK_BYTES];
__device__ unsigned char d_w2t_hi[3 * BCHUNK_BYTES];
__device__ unsigned char d_w2t_lo[3 * BCHUNK_BYTES];

// ---------------- helpers ----------------
__device__ __forceinline__ uint32_t smem_u32(const void* p) {
    uint32_t a;
    asm("{ .reg .u64 t; cvta.to.shared.u64 t, %1; cvt.u32.u64 %0, t; }" : "=r"(a) : "l"(p));
    return a;
}
__device__ __forceinline__ uint32_t packbf2(float a, float b) {
    __nv_bfloat162 t;
    t.x = __float2bfloat16(a);
    t.y = __float2bfloat16(b);
    return *reinterpret_cast<uint32_t*>(&t);
}
__device__ __forceinline__ uint32_t split2(float a, float b, float& ra, float& rb) {
    __nv_bfloat16 ha = __float2bfloat16(a), hb = __float2bfloat16(b);
    ra = a - __bfloat162float(ha);
    rb = b - __bfloat162float(hb);
    __nv_bfloat162 t; t.x = ha; t.y = hb;
    return *reinterpret_cast<uint32_t*>(&t);
}
__device__ __forceinline__ void mma16816(float* c, const uint32_t* a,
                                         uint32_t b0, uint32_t b1) {
    asm volatile(
        "mma.sync.aligned.m16n8k16.row.col.f32.bf16.bf16.f32 "
        "{%0,%1,%2,%3}, {%4,%5,%6,%7}, {%8,%9}, {%0,%1,%2,%3};"
        : "+f"(c[0]), "+f"(c[1]), "+f"(c[2]), "+f"(c[3])
        : "r"(a[0]), "r"(a[1]), "r"(a[2]), "r"(a[3]), "r"(b0), "r"(b1));
}
__device__ __forceinline__ void ldsm_x4(uint32_t* r, uint32_t addr) {
    asm volatile("ldmatrix.sync.aligned.m8n8.x4.shared.b16 {%0,%1,%2,%3}, [%4];"
        : "=r"(r[0]), "=r"(r[1]), "=r"(r[2]), "=r"(r[3]) : "r"(addr));
}
__device__ __forceinline__ void ldsm_x2(uint32_t* r, uint32_t addr) {
    asm volatile("ldmatrix.sync.aligned.m8n8.x2.shared.b16 {%0,%1}, [%2];"
        : "=r"(r[0]), "=r"(r[1]) : "r"(addr));
}
#define CPA16(dst, src) asm volatile("cp.async.ca.shared.global [%0], [%1], 16;" :: "r"(dst), "l"(src))
#define CPA_COMMIT()    asm volatile("cp.async.commit_group;" ::: "memory")
#define CPA_WAIT0()     asm volatile("cp.async.wait_group 0;" ::: "memory")

// ---------------------------------------------------------------------------
// prep_kernel: blocks [0,128) = gia/gjt GEMM; blocks [128,568) = weight split.
// ---------------------------------------------------------------------------
__global__ __launch_bounds__(256)
void prep_kernel(const float* __restrict__ g,
                 const float* __restrict__ W1,
                 const float* __restrict__ b1,
                 const float* __restrict__ W2) {
    const int tid = threadIdx.x;
    if (blockIdx.x < 128) {
        __shared__ float gs[32][64];
        __shared__ float Ws[64][80];
        const int mt = blockIdx.x >> 2, ct = blockIdx.x & 3;
        const int half = ct >> 1, ncol = (ct & 1) * 80;
        const int tx = tid & 15, ty = tid >> 4;

        float acc[2][5];
#pragma unroll
        for (int a = 0; a < 2; a++)
#pragma unroll
            for (int j = 0; j < 5; j++) acc[a][j] = 0.f;

        for (int kc = 0; kc < 8; kc++) {
#pragma unroll
            for (int r = 0; r < 8; r++) {
                const int ix = tid + r * 256, rr = ix >> 6, kk = ix & 63;
                gs[rr][kk] = g[(size_t)(mt * 32 + rr) * DIM + kc * 64 + kk];
            }
#pragma unroll
            for (int r = 0; r < 20; r++) {
                const int ix = tid + r * 256, kk = ix / 80, nn = ix % 80;
                const int col = ncol + nn;
                Ws[kk][nn] = (col < HID)
                    ? W1[(size_t)(half * DIM + kc * 64 + kk) * HID + col] : 0.f;
            }
            __syncthreads();
#pragma unroll 4
            for (int k = 0; k < 64; k++) {
                const float a0 = gs[ty * 2][k], a1 = gs[ty * 2 + 1][k];
#pragma unroll
                for (int j = 0; j < 5; j++) {
                    const float w = Ws[k][tx + 16 * j];
                    acc[0][j] += a0 * w;
                    acc[1][j] += a1 * w;
                }
            }
            __syncthreads();
        }
#pragma unroll
        for (int rr = 0; rr < 2; rr++) {
            const int row = mt * 32 + ty * 2 + rr;
#pragma unroll
            for (int j = 0; j < 5; j++) {
                const int col = ncol + tx + 16 * j;
                if (col < HID) {
                    if (!half) d_gia[row * HID + col] = acc[rr][j] + b1[col];
                    else       d_gjt[row * 152 + col] = acc[rr][j];
                }
            }
        }
        if (ct == 3 && tid < 64)
            d_gjt[(mt * 32 + (tid >> 1)) * 152 + HID + (tid & 1)] = 0.f;
        return;
    }

    // ---- weight split part ----
    const int idx = (blockIdx.x - 128) * 256 + tid;
    const int NW1 = 8 * HPAD * 64;
    if (idx < NW1) {
        const int c = idx / (HPAD * 64), r = idx % (HPAD * 64), n = r / 64, k = r % 64;
        const int d = c * 64 + k;
        const float v = (n < HID) ? W1[(size_t)(2 * DIM + d) * HID + n] : 0.f;
        __nv_bfloat16 hi = __float2bfloat16(v);
        __nv_bfloat16 lo = __float2bfloat16(v - __bfloat162float(hi));
        const uint32_t off = c * BCHUNK_BYTES + n * RS1 + k * 2;
        *(__nv_bfloat16*)(d_w1t_hi + off) = hi;
        *(__nv_bfloat16*)(d_w1t_lo + off) = lo;
    } else if (idx < NW1 + 3 * HPAD * 64) {
        const int i2 = idx - NW1;
        const int c = i2 / (HPAD * 64), r = i2 % (HPAD * 64), n = r / 64, k = r % 64;
        const int kk = c * 64 + k;
        const float v = (n < HID && kk < HID) ? W2[(size_t)kk * HID + n] : 0.f;
        __nv_bfloat16 hi = __float2bfloat16(v);
        __nv_bfloat16 lo = __float2bfloat16(v - __bfloat162float(hi));
        const uint32_t off = c * BCHUNK_BYTES + n * RS1 + k * 2;
        *(__nv_bfloat16*)(d_w2t_hi + off) = hi;
        *(__nv_bfloat16*)(d_w2t_lo + off) = lo;
    }
}

// ---------------------------------------------------------------------------
// Main pair MLP. CTA = (span i, 64 window rows). 256 threads, 8 warps 2Mx4N,
// warp tile 32(M) x 40(N). 2 CTAs/SM so phases of one CTA overlap mma of the
// other — that is the concurrency mechanism (no in-CTA double buffering).
// ---------------------------------------------------------------------------
__global__ __launch_bounds__(NTHREADS, 2)
void pair_mma_kernel(const float* __restrict__ g,
                     const float* __restrict__ sm,
                     const float* __restrict__ b2,
                     const float* __restrict__ W3,
                     const float* __restrict__ b3,
                     float* __restrict__ out) {
    extern __shared__ unsigned char smem[];
    const uint32_t sbase = smem_u32(smem);
    const int tid  = threadIdx.x;
    const int wid  = tid >> 5, lane = tid & 31;
    const int g8   = lane >> 2, tig = lane & 3;
    const int wm   = wid & 1, wn = wid >> 1;
    const int i    = blockIdx.y;
    const int k0   = blockIdx.x * MTILE;

    int*   jrow = (int*)(smem + OFF_JROW);
    float* smjf = (float*)(smem + OFF_SMJ);
    float* gis  = (float*)(smem + OFF_GIS);
    float* gias = (float*)(smem + OFF_GIAS);
    float* b2s  = (float*)(smem + OFF_B2S);
    float* w3s  = (float*)(smem + OFF_W3S);
    float* sred = (float*)(smem + OFF_SRED);

    // ---- init ----
    gis[tid] = g[(size_t)i * DIM + tid];
    gis[tid + 256] = g[(size_t)i * DIM + tid + 256];
    if (tid < HPAD) {
        const bool v = tid < HID;
        gias[tid] = v ? d_gia[i * HID + tid] : 0.f;
        b2s[tid]  = v ? b2[tid] : 0.f;
        w3s[tid]  = v ? W3[tid] : 0.f;
    }
    if (tid < MTILE) {
        const int k = k0 + tid;
        int j = i - WIN + k;
        int jc = j < 0 ? 0 : (j > N_SPANS - 1 ? N_SPANS - 1 : j);
        jrow[tid] = jc;
        smjf[tid] = sm[jc];
    }
    __syncthreads();

    // ---- stage gjt tile (consumed after layer-1; overlaps compute) ----
    {
        const int m = tid >> 2, q = tid & 3;
        const uint4* src = (const uint4*)(d_gjt + jrow[m] * 152);
        uint4* dst = (uint4*)(smem + OFF_GJ + m * 608);
#pragma unroll
        for (int r = 0; r < 10; r++) {
            const int ix = q * 10 + r;
            if (ix < 38) dst[ix] = src[ix];
        }
    }

    float acc[2][5][4];
#pragma unroll
    for (int a = 0; a < 2; a++)
#pragma unroll
        for (int b = 0; b < 5; b++)
#pragma unroll
            for (int e = 0; e < 4; e++) acc[a][b][e] = 0.f;

    const int bm  = tid >> 2;           // build row (0..63)
    const int bq  = (tid & 3) * 16;     // build k-offset (floats)
    const int jcm = jrow[bm];
    const int rowA = wm * 32 + g8;      // fragment base A row

    // ldmatrix lane addresses
    const uint32_t aAddrH  = sbase + OFF_A_HI + (wm * 32 + (lane & 15)) * RS1 + ((lane >> 4) << 4);
    const uint32_t aAddrL  = aAddrH + (OFF_A_LO - OFF_A_HI);
    const uint32_t a2AddrH = sbase + OFF_A2_HI + (wm * 32 + (lane & 15)) * RS2 + ((lane >> 4) << 4);
    const uint32_t a2AddrL = a2AddrH + (OFF_A2_LO - OFF_A2_HI);
    const uint32_t bAddrH  = sbase + OFF_B_HI +
        (wn * 40 + (lane & 7) + ((lane >> 4) << 3)) * RS1 + (((lane >> 3) & 1) << 4);
    const uint32_t bAddrL  = bAddrH + BCHUNK_BYTES;
    const uint32_t bAddr2H = sbase + OFF_B_HI +
        (wn * 40 + 32 + (lane & 7)) * RS1 + (((lane >> 3) & 1) << 4);
    const uint32_t bAddr2L = bAddr2H + BCHUNK_BYTES;

    // prefetch gj chunk 0 (16 floats per thread)
    float4 pgj[4];
    {
        const float4* gj4 = (const float4*)(g + (size_t)jcm * DIM + bq);
#pragma unroll
        for (int v = 0; v < 4; v++) pgj[v] = gj4[v];
    }

    // ================= layer 1: K=512, 8 chunks of 64 =================
    for (int c = 0; c < 8; c++) {
        if (c) __syncthreads();   // prior mma done before overwriting A/B
        // issue B chunk copy (cp.async)
        {
            const unsigned char* sh = d_w1t_hi + c * BCHUNK_BYTES;
            const unsigned char* sl = d_w1t_lo + c * BCHUNK_BYTES;
#pragma unroll
            for (int r = 0; r < 6; r++) {
                const int ix = tid + r * NTHREADS;
                if (ix < BCHUNK_V16) {
                    CPA16(sbase + OFF_B_HI + ix * 16, sh + ix * 16);
                    CPA16(sbase + OFF_B_LO + ix * 16, sl + ix * 16);
                }
            }
            CPA_COMMIT();
        }
        // build A chunk from prefetched regs
        {
            const float4* gi4 = (const float4*)(gis + c * 64 + bq);
            unsigned char* ah = smem + OFF_A_HI + bm * RS1 + bq * 2;
            unsigned char* al = smem + OFF_A_LO + bm * RS1 + bq * 2;
#pragma unroll
            for (int v = 0; v < 4; v++) {
                const float4 a4 = pgj[v], i4 = gi4[v];
                float p0 = a4.x * i4.x, p1 = a4.y * i4.y;
                float p2 = a4.z * i4.z, p3 = a4.w * i4.w;
                float r0, r1, r2, r3;
                uint2 uh, ul;
                uh.x = split2(p0, p1, r0, r1);
                uh.y = split2(p2, p3, r2, r3);
                ul.x = packbf2(r0, r1);
                ul.y = packbf2(r2, r3);
                *(uint2*)(ah + v * 8) = uh;
                *(uint2*)(al + v * 8) = ul;
            }
        }
        // prefetch next gj chunk (completes under the mma below)
        if (c < 7) {
            const float4* gj4 = (const float4*)(g + (size_t)jcm * DIM + (c + 1) * 64 + bq);
#pragma unroll
            for (int v = 0; v < 4; v++) pgj[v] = gj4[v];
        }
        CPA_WAIT0();
        __syncthreads();

        // mma over 4 k16 steps
#pragma unroll
        for (int ks = 0; ks < 4; ks++) {
            const uint32_t ko = ks * 32;
            uint32_t Ah0[4], Ah1[4], Al0[4], Al1[4];
            ldsm_x4(Ah0, aAddrH + ko);
            ldsm_x4(Ah1, aAddrH + 16 * RS1 + ko);
            ldsm_x4(Al0, aAddrL + ko);
            ldsm_x4(Al1, aAddrL + 16 * RS1 + ko);
#pragma unroll
            for (int p2 = 0; p2 < 2; p2++) {
                uint32_t BH[4], BL[4];
                ldsm_x4(BH, bAddrH + p2 * 16 * RS1 + ko);
                ldsm_x4(BL, bAddrL + p2 * 16 * RS1 + ko);
                const int nA = 2 * p2, nB = 2 * p2 + 1;
                mma16816(acc[0][nA], Ah0, BH[0], BH[1]);
                mma16816(acc[1][nA], Ah1, BH[0], BH[1]);
                mma16816(acc[0][nA], Al0, BH[0], BH[1]);
                mma16816(acc[1][nA], Al1, BH[0], BH[1]);
                mma16816(acc[0][nA], Ah0, BL[0], BL[1]);
                mma16816(acc[1][nA], Ah1, BL[0], BL[1]);
                mma16816(acc[0][nB], Ah0, BH[2], BH[3]);
                mma16816(acc[1][nB], Ah1, BH[2], BH[3]);
                mma16816(acc[0][nB], Al0, BH[2], BH[3]);
                mma16816(acc[1][nB], Al1, BH[2], BH[3]);
                mma16816(acc[0][nB], Ah0, BL[2], BL[3]);
                mma16816(acc[1][nB], Ah1, BL[2], BL[3]);
            }
            {
                uint32_t BH[2], BL[2];
                ldsm_x2(BH, bAddr2H + ko);
                ldsm_x2(BL, bAddr2L + ko);
                mma16816(acc[0][4], Ah0, BH[0], BH[1]);
                mma16816(acc[1][4], Ah1, BH[0], BH[1]);
                mma16816(acc[0][4], Al0, BH[0], BH[1]);
                mma16816(acc[1][4], Al1, BH[0], BH[1]);
                mma16816(acc[0][4], Ah0, BL[0], BL[1]);
                mma16816(acc[1][4], Ah1, BL[0], BL[1]);
            }
        }
    }

    // ---- layer-1 epilogue: h1 = relu(acc + gia + gjt) (in registers) ----
#pragma unroll
    for (int mf = 0; mf < 2; mf++) {
        const int r = rowA + mf * 16;
#pragma unroll
        for (int nf = 0; nf < 5; nf++) {
            const int n0 = wn * 40 + nf * 8 + tig * 2;
            if (n0 < HID) {
                const float2 ga = *(const float2*)(gias + n0);
                const float2 gj0 = *(const float2*)(smem + OFF_GJ + r * 608 + n0 * 4);
                const float2 gj1 = *(const float2*)(smem + OFF_GJ + (r + 8) * 608 + n0 * 4);
                acc[mf][nf][0] = fmaxf(acc[mf][nf][0] + gj0.x + ga.x, 0.f);
                acc[mf][nf][1] = fmaxf(acc[mf][nf][1] + gj0.y + ga.y, 0.f);
                acc[mf][nf][2] = fmaxf(acc[mf][nf][2] + gj1.x + ga.x, 0.f);
                acc[mf][nf][3] = fmaxf(acc[mf][nf][3] + gj1.y + ga.y, 0.f);
            } else {
                acc[mf][nf][0] = acc[mf][nf][1] = acc[mf][nf][2] = acc[mf][nf][3] = 0.f;
            }
        }
    }
    __syncthreads();   // all gjt reads done before A2 overwrites that region

    // ---- write h1 split tiles into A2 ----
#pragma unroll
    for (int mf = 0; mf < 2; mf++) {
        const int r = rowA + mf * 16;
#pragma unroll
        for (int nf = 0; nf < 5; nf++) {
            const int n0 = wn * 40 + nf * 8 + tig * 2;
            float r0, r1;
            uint32_t h = split2(acc[mf][nf][0], acc[mf][nf][1], r0, r1);
            *(uint32_t*)(smem + OFF_A2_HI + r * RS2 + n0 * 2) = h;
            *(uint32_t*)(smem + OFF_A2_LO + r * RS2 + n0 * 2) = packbf2(r0, r1);
            h = split2(acc[mf][nf][2], acc[mf][nf][3], r0, r1);
            *(uint32_t*)(smem + OFF_A2_HI + (r + 8) * RS2 + n0 * 2) = h;
            *(uint32_t*)(smem + OFF_A2_LO + (r + 8) * RS2 + n0 * 2) = packbf2(r0, r1);
        }
    }

#pragma unroll
    for (int a = 0; a < 2; a++)
#pragma unroll
        for (int b = 0; b < 5; b++)
#pragma unroll
            for (int e = 0; e < 4; e++) acc[a][b][e] = 0.f;

    // ================= layer 2: K=160 (3 chunks: 64,64,32) =================
    for (int c2 = 0; c2 < 3; c2++) {
        __syncthreads();   // A2 writes (c2==0) / prior mma B reads done
        {
            const unsigned char* sh = d_w2t_hi + c2 * BCHUNK_BYTES;
            const unsigned char* sl = d_w2t_lo + c2 * BCHUNK_BYTES;
#pragma unroll
            for (int r = 0; r < 6; r++) {
                const int ix = tid + r * NTHREADS;
                if (ix < BCHUNK_V16) {
                    CPA16(sbase + OFF_B_HI + ix * 16, sh + ix * 16);
                    CPA16(sbase + OFF_B_LO + ix * 16, sl + ix * 16);
                }
            }
            CPA_COMMIT();
            CPA_WAIT0();
        }
        __syncthreads();
        const int nks = (c2 < 2) ? 4 : 2;
        for (int ks = 0; ks < nks; ks++) {
            const uint32_t ko  = ks * 32;
            const uint32_t ko2 = c2 * 128 + ks * 32;
            uint32_t Ah0[4], Ah1[4], Al0[4], Al1[4];
            ldsm_x4(Ah0, a2AddrH + ko2);
            ldsm_x4(Ah1, a2AddrH + 16 * RS2 + ko2);
            ldsm_x4(Al0, a2AddrL + ko2);
            ldsm_x4(Al1, a2AddrL + 16 * RS2 + ko2);
#pragma unroll
            for (int p2 = 0; p2 < 2; p2++) {
                uint32_t BH[4], BL[4];
                ldsm_x4(BH, bAddrH + p2 * 16 * RS1 + ko);
                ldsm_x4(BL, bAddrL + p2 * 16 * RS1 + ko);
                const int nA = 2 * p2, nB = 2 * p2 + 1;
                mma16816(acc[0][nA], Ah0, BH[0], BH[1]);
                mma16816(acc[1][nA], Ah1, BH[0], BH[1]);
                mma16816(acc[0][nA], Al0, BH[0], BH[1]);
                mma16816(acc[1][nA], Al1, BH[0], BH[1]);
                mma16816(acc[0][nA], Ah0, BL[0], BL[1]);
                mma16816(acc[1][nA], Ah1, BL[0], BL[1]);
                mma16816(acc[0][nB], Ah0, BH[2], BH[3]);
                mma16816(acc[1][nB], Ah1, BH[2], BH[3]);
                mma16816(acc[0][nB], Al0, BH[2], BH[3]);
                mma16816(acc[1][nB], Al1, BH[2], BH[3]);
                mma16816(acc[0][nB], Ah0, BL[2], BL[3]);
                mma16816(acc[1][nB], Ah1, BL[2], BL[3]);
            }
            {
                uint32_t BH[2], BL[2];
                ldsm_x2(BH, bAddr2H + ko);
                ldsm_x2(BL, bAddr2L + ko);
                mma16816(acc[0][4], Ah0, BH[0], BH[1]);
                mma16816(acc[1][4], Ah1, BH[0], BH[1]);
                mma16816(acc[0][4], Al0, BH[0], BH[1]);
                mma16816(acc[1][4], Al1, BH[0], BH[1]);
                mma16816(acc[0][4], Ah0, BL[0], BL[1]);
                mma16816(acc[1][4], Ah1, BL[0], BL[1]);
            }
        }
    }

    // ---- final: s = relu(acc2 + b2) . W3, quad-shuffle reduce ----
#pragma unroll
    for (int mf = 0; mf < 2; mf++) {
        float pr = 0.f, pr8 = 0.f;
#pragma unroll
        for (int nf = 0; nf < 5; nf++) {
            const int n0 = wn * 40 + nf * 8 + tig * 2;
            const float2 bb = *(const float2*)(b2s + n0);
            const float2 ww = *(const float2*)(w3s + n0);
            pr  += fmaxf(acc[mf][nf][0] + bb.x, 0.f) * ww.x
                 + fmaxf(acc[mf][nf][1] + bb.y, 0.f) * ww.y;
            pr8 += fmaxf(acc[mf][nf][2] + bb.x, 0.f) * ww.x
                 + fmaxf(acc[mf][nf][3] + bb.y, 0.f) * ww.y;
        }
        pr  += __shfl_xor_sync(0xffffffffu, pr, 1);
        pr  += __shfl_xor_sync(0xffffffffu, pr, 2);
        pr8 += __shfl_xor_sync(0xffffffffu, pr8, 1);
        pr8 += __shfl_xor_sync(0xffffffffu, pr8, 2);
        if (tig == 0) {
            sred[wn * MTILE + rowA + mf * 16]     = pr;
            sred[wn * MTILE + rowA + mf * 16 + 8] = pr8;
        }
    }
    __syncthreads();

    if (tid < MTILE) {
        const float s = sred[tid] + sred[MTILE + tid] + sred[2 * MTILE + tid] + sred[3 * MTILE + tid];
        const int k = k0 + tid;
        if (k < WIN) {
            const int j = i - WIN + k;
            out[i * OUTW + k] = (j >= 0) ? (sm[i] + smjf[tid] + s + b3[0]) : 0.f;
        } else if (k == WIN) {
            out[i * OUTW + k] = 0.f;  // trailing epsilon column
        }
    }
}

// ---------------------------------------------------------------------------
extern "C" void kernel_launch(void* const* d_in, const int* in_sizes, int n_in,
                              void* d_out, int out_size) {
    const float* g  = (const float*)d_in[0];
    const float* sm = (const float*)d_in[1];
    const float* W1 = (const float*)d_in[2];
    const float* b1 = (const float*)d_in[3];
    const float* W2 = (const float*)d_in[4];
    const float* b2 = (const float*)d_in[5];
    const float* W3 = (const float*)d_in[6];
    const float* b3 = (const float*)d_in[7];
    float* out = (float*)d_out;

    cudaFuncSetAttribute(pair_mma_kernel, cudaFuncAttributeMaxDynamicSharedMemorySize,
                         SMEM_TOTAL);

    // 128 GEMM blocks + 440 weight-split blocks (11*160*64/256)
    prep_kernel<<<128 + 440, 256>>>(g, W1, b1, W2);
    pair_mma_kernel<<<dim3(4, N_SPANS), NTHREADS, SMEM_TOTAL>>>(g, sm, b2, W3, b3, out);
}

// round 15
// speedup vs baseline: 1.2693x; 1.2647x over previous
#include <cuda_runtime.h>
#include <cuda_bf16.h>
#include <stdint.h>

// ---------------- problem constants ----------------
#define N_SPANS 1024
#define DIM     512
#define HID     150
#define WIN     250
#define OUTW    (WIN + 1)
#define HPAD    160
#define NTHREADS 256
#define MTILE   64

// row strides (bytes) for bf16 A tiles (multiples of 16 for ldmatrix)
#define RS1 144        // layer-1 A: 64 bf16 + pad
#define RS2 336        // layer-2 A (h1): 160 bf16 + pad

// fragment-direct B: per k16-step: 160 n x 4 klane x 8 bytes = 5120 B
#define BSTEP 5120
#define NW1REC (32 * HPAD * 4)      // 20480 records, layer-1 (K=512 -> 32 steps)
#define NW2REC (10 * HPAD * 4)      // 6400 records,  layer-2 (K=160 -> 10 steps)

// ---------------- smem layout (bytes) ----------------
#define OFF_JROW 0                  // 64 ints
#define OFF_SMJ  256                // 64 floats
#define OFF_GIS  512                // 512 floats
#define OFF_GIAS 2560               // 160 floats
#define OFF_B2S  3200               // 160 floats
#define OFF_W3S  3840               // 160 floats
#define OFF_SRED 4480               // 4 x 64 floats -> ends 5504
#define OFF_A0_HI 5504              // 64 x RS1
#define OFF_A0_LO (OFF_A0_HI + MTILE*RS1)
#define OFF_A2_HI (OFF_A0_LO + MTILE*RS1)      // 64 x RS2 (also hosts A ping1)
#define OFF_A2_LO (OFF_A2_HI + MTILE*RS2)
#define SMEM_TOTAL (OFF_A2_LO + MTILE*RS2)     // 66944 -> 2 CTAs/SM
#define APING (OFF_A2_HI - OFF_A0_HI)          // ping1 aliases A2 region (time-separated)

// ---------------- device scratch ----------------
__device__ float d_gia[N_SPANS * HID];          // g@W1a + b1
__device__ float d_gjt[N_SPANS * 152];          // g@W1b, padded rows
// fragment-direct split weights
__device__ unsigned char d_w1f_hi[NW1REC * 8];
__device__ unsigned char d_w1f_lo[NW1REC * 8];
__device__ unsigned char d_w2f_hi[NW2REC * 8];
__device__ unsigned char d_w2f_lo[NW2REC * 8];

// ---------------- helpers ----------------
__device__ __forceinline__ uint32_t smem_u32(const void* p) {
    uint32_t a;
    asm("{ .reg .u64 t; cvta.to.shared.u64 t, %1; cvt.u32.u64 %0, t; }" : "=r"(a) : "l"(p));
    return a;
}
__device__ __forceinline__ uint32_t packbf2(float a, float b) {
    __nv_bfloat162 t;
    t.x = __float2bfloat16(a);
    t.y = __float2bfloat16(b);
    return *reinterpret_cast<uint32_t*>(&t);
}
__device__ __forceinline__ uint32_t split2(float a, float b, float& ra, float& rb) {
    __nv_bfloat16 ha = __float2bfloat16(a), hb = __float2bfloat16(b);
    ra = a - __bfloat162float(ha);
    rb = b - __bfloat162float(hb);
    __nv_bfloat162 t; t.x = ha; t.y = hb;
    return *reinterpret_cast<uint32_t*>(&t);
}
__device__ __forceinline__ void mma16816(float* c, const uint32_t* a,
                                         uint32_t b0, uint32_t b1) {
    asm volatile(
        "mma.sync.aligned.m16n8k16.row.col.f32.bf16.bf16.f32 "
        "{%0,%1,%2,%3}, {%4,%5,%6,%7}, {%8,%9}, {%0,%1,%2,%3};"
        : "+f"(c[0]), "+f"(c[1]), "+f"(c[2]), "+f"(c[3])
        : "r"(a[0]), "r"(a[1]), "r"(a[2]), "r"(a[3]), "r"(b0), "r"(b1));
}
__device__ __forceinline__ void ldsm_x4(uint32_t* r, uint32_t addr) {
    asm volatile("ldmatrix.sync.aligned.m8n8.x4.shared.b16 {%0,%1,%2,%3}, [%4];"
        : "=r"(r[0]), "=r"(r[1]), "=r"(r[2]), "=r"(r[3]) : "r"(addr));
}

// ---------------------------------------------------------------------------
// prep_kernel: blocks [0,128) = gia/gjt GEMM; blocks >=128 = fragment-direct
// weight packing. Record (s, n, klane) holds {W[k0][n], W[k0+1][n],
// W[k0+8][n], W[k0+9][n]} as bf16 hi/lo, k0 = s*16 + klane*2 — exactly the
// m16n8k16 col-major B fragment for lane: klane = lane&3, n' = lane>>2.
// ---------------------------------------------------------------------------
__global__ __launch_bounds__(256)
void prep_kernel(const float* __restrict__ g,
                 const float* __restrict__ W1,
                 const float* __restrict__ b1,
                 const float* __restrict__ W2) {
    const int tid = threadIdx.x;
    if (blockIdx.x < 128) {
        __shared__ float gs[32][64];
        __shared__ float Ws[64][80];
        const int mt = blockIdx.x >> 2, ct = blockIdx.x & 3;
        const int half = ct >> 1, ncol = (ct & 1) * 80;
        const int tx = tid & 15, ty = tid >> 4;

        float acc[2][5];
#pragma unroll
        for (int a = 0; a < 2; a++)
#pragma unroll
            for (int j = 0; j < 5; j++) acc[a][j] = 0.f;

        for (int kc = 0; kc < 8; kc++) {
#pragma unroll
            for (int r = 0; r < 8; r++) {
                const int ix = tid + r * 256, rr = ix >> 6, kk = ix & 63;
                gs[rr][kk] = g[(size_t)(mt * 32 + rr) * DIM + kc * 64 + kk];
            }
#pragma unroll
            for (int r = 0; r < 20; r++) {
                const int ix = tid + r * 256, kk = ix / 80, nn = ix % 80;
                const int col = ncol + nn;
                Ws[kk][nn] = (col < HID)
                    ? W1[(size_t)(half * DIM + kc * 64 + kk) * HID + col] : 0.f;
            }
            __syncthreads();
#pragma unroll 4
            for (int k = 0; k < 64; k++) {
                const float a0 = gs[ty * 2][k], a1 = gs[ty * 2 + 1][k];
#pragma unroll
                for (int j = 0; j < 5; j++) {
                    const float w = Ws[k][tx + 16 * j];
                    acc[0][j] += a0 * w;
                    acc[1][j] += a1 * w;
                }
            }
            __syncthreads();
        }
#pragma unroll
        for (int rr = 0; rr < 2; rr++) {
            const int row = mt * 32 + ty * 2 + rr;
#pragma unroll
            for (int j = 0; j < 5; j++) {
                const int col = ncol + tx + 16 * j;
                if (col < HID) {
                    if (!half) d_gia[row * HID + col] = acc[rr][j] + b1[col];
                    else       d_gjt[row * 152 + col] = acc[rr][j];
                }
            }
        }
        if (ct == 3 && tid < 64)
            d_gjt[(mt * 32 + (tid >> 1)) * 152 + HID + (tid & 1)] = 0.f;
        return;
    }

    // ---- fragment-direct weight packing ----
    const int idx = (blockIdx.x - 128) * 256 + tid;
    float v[4];
    if (idx < NW1REC) {
        const int s = idx / (HPAD * 4), r = idx % (HPAD * 4), n = r >> 2, kl = r & 3;
        const int k0 = s * 16 + kl * 2;
#pragma unroll
        for (int e = 0; e < 4; e++) {
            const int k = k0 + (e >> 1) * 8 + (e & 1);
            v[e] = (n < HID) ? W1[(size_t)(2 * DIM + k) * HID + n] : 0.f;
        }
        uint2 uh, ul;
        float r0, r1, r2, r3;
        uh.x = split2(v[0], v[1], r0, r1);
        uh.y = split2(v[2], v[3], r2, r3);
        ul.x = packbf2(r0, r1);
        ul.y = packbf2(r2, r3);
        ((uint2*)d_w1f_hi)[idx] = uh;
        ((uint2*)d_w1f_lo)[idx] = ul;
    } else if (idx < NW1REC + NW2REC) {
        const int i2 = idx - NW1REC;
        const int s = i2 / (HPAD * 4), r = i2 % (HPAD * 4), n = r >> 2, kl = r & 3;
        const int k0 = s * 16 + kl * 2;
#pragma unroll
        for (int e = 0; e < 4; e++) {
            const int k = k0 + (e >> 1) * 8 + (e & 1);
            v[e] = (n < HID && k < HID) ? W2[(size_t)k * HID + n] : 0.f;
        }
        uint2 uh, ul;
        float r0, r1, r2, r3;
        uh.x = split2(v[0], v[1], r0, r1);
        uh.y = split2(v[2], v[3], r2, r3);
        ul.x = packbf2(r0, r1);
        ul.y = packbf2(r2, r3);
        ((uint2*)d_w2f_hi)[i2] = uh;
        ((uint2*)d_w2f_lo)[i2] = ul;
    }
}

// ---------------------------------------------------------------------------
// Main pair MLP. CTA = (span i, 64 window rows), 256 threads, 8 warps 2Mx4N,
// 2 CTAs/SM. B operands: direct LDG of fragment-direct records (L2-resident).
// A tile ping-pongs (ping1 aliases A2 region) -> ONE sync per chunk; layer 2
// is sync-free.
// ---------------------------------------------------------------------------
__global__ __launch_bounds__(NTHREADS, 2)
void pair_mma_kernel(const float* __restrict__ g,
                     const float* __restrict__ sm,
                     const float* __restrict__ b2,
                     const float* __restrict__ W3,
                     const float* __restrict__ b3,
                     float* __restrict__ out) {
    extern __shared__ unsigned char smem[];
    const uint32_t sbase = smem_u32(smem);
    const int tid  = threadIdx.x;
    const int wid  = tid >> 5, lane = tid & 31;
    const int g8   = lane >> 2, tig = lane & 3;
    const int wm   = wid & 1, wn = wid >> 1;
    const int i    = blockIdx.y;
    const int k0   = blockIdx.x * MTILE;

    int*   jrow = (int*)(smem + OFF_JROW);
    float* smjf = (float*)(smem + OFF_SMJ);
    float* gis  = (float*)(smem + OFF_GIS);
    float* gias = (float*)(smem + OFF_GIAS);
    float* b2s  = (float*)(smem + OFF_B2S);
    float* w3s  = (float*)(smem + OFF_W3S);
    float* sred = (float*)(smem + OFF_SRED);

    // ---- init ----
    gis[tid] = g[(size_t)i * DIM + tid];
    gis[tid + 256] = g[(size_t)i * DIM + tid + 256];
    if (tid < HPAD) {
        const bool v = tid < HID;
        gias[tid] = v ? d_gia[i * HID + tid] : 0.f;
        b2s[tid]  = v ? b2[tid] : 0.f;
        w3s[tid]  = v ? W3[tid] : 0.f;
    }
    if (tid < MTILE) {
        const int k = k0 + tid;
        int j = i - WIN + k;
        int jc = j < 0 ? 0 : (j > N_SPANS - 1 ? N_SPANS - 1 : j);
        jrow[tid] = jc;
        smjf[tid] = sm[jc];
    }
    __syncthreads();

    float acc[2][5][4];
#pragma unroll
    for (int a = 0; a < 2; a++)
#pragma unroll
        for (int b = 0; b < 5; b++)
#pragma unroll
            for (int e = 0; e < 4; e++) acc[a][b][e] = 0.f;

    const int bm  = tid >> 2;           // build row (0..63)
    const int bq  = (tid & 3) * 16;     // build k-offset (floats)
    const int jcm = jrow[bm];
    const int rowA = wm * 32 + g8;      // fragment base A row

    // ldmatrix lane addresses (ping 0 base)
    const uint32_t aAddrH  = sbase + OFF_A0_HI + (wm * 32 + (lane & 15)) * RS1 + ((lane >> 4) << 4);
    const uint32_t aAddrL  = aAddrH + (OFF_A0_LO - OFF_A0_HI);
    const uint32_t a2AddrH = sbase + OFF_A2_HI + (wm * 32 + (lane & 15)) * RS2 + ((lane >> 4) << 4);
    const uint32_t a2AddrL = a2AddrH + (OFF_A2_LO - OFF_A2_HI);

    // fragment-direct B lane offset
    const uint32_t boff = ((uint32_t)(wn * 40 + (lane >> 2)) * 4 + (lane & 3)) * 8;

    // prefetch gj chunk 0 (16 floats per thread)
    float4 pgj[4];
    {
        const float4* gj4 = (const float4*)(g + (size_t)jcm * DIM + bq);
#pragma unroll
        for (int v = 0; v < 4; v++) pgj[v] = gj4[v];
    }

    // ---- build A(0) into ping0, prefetch gj chunk 1 ----
    {
        const float4* gi4 = (const float4*)(gis + bq);
        unsigned char* ah = smem + OFF_A0_HI + bm * RS1 + bq * 2;
        unsigned char* al = smem + OFF_A0_LO + bm * RS1 + bq * 2;
#pragma unroll
        for (int v = 0; v < 4; v++) {
            const float4 a4 = pgj[v], i4 = gi4[v];
            float p0 = a4.x * i4.x, p1 = a4.y * i4.y;
            float p2 = a4.z * i4.z, p3 = a4.w * i4.w;
            float r0, r1, r2, r3;
            uint2 uh, ul;
            uh.x = split2(p0, p1, r0, r1);
            uh.y = split2(p2, p3, r2, r3);
            ul.x = packbf2(r0, r1);
            ul.y = packbf2(r2, r3);
            *(uint2*)(ah + v * 8) = uh;
            *(uint2*)(al + v * 8) = ul;
        }
        const float4* gj4 = (const float4*)(g + (size_t)jcm * DIM + 64 + bq);
#pragma unroll
        for (int v = 0; v < 4; v++) pgj[v] = gj4[v];
    }
    __syncthreads();

    // ================= layer 1: K=512, 8 chunks of 64 =================
    for (int c = 0; c < 8; c++) {
        const uint32_t pcur = (c & 1) ? APING : 0;
        // build A(c+1) into the other ping (overlaps other warps' mma below)
        if (c < 7) {
            const uint32_t pnxt = (c & 1) ? 0 : APING;
            const float4* gi4 = (const float4*)(gis + (c + 1) * 64 + bq);
            unsigned char* ah = smem + OFF_A0_HI + pnxt + bm * RS1 + bq * 2;
            unsigned char* al = smem + OFF_A0_LO + pnxt + bm * RS1 + bq * 2;
#pragma unroll
            for (int v = 0; v < 4; v++) {
                const float4 a4 = pgj[v], i4 = gi4[v];
                float p0 = a4.x * i4.x, p1 = a4.y * i4.y;
                float p2 = a4.z * i4.z, p3 = a4.w * i4.w;
                float r0, r1, r2, r3;
                uint2 uh, ul;
                uh.x = split2(p0, p1, r0, r1);
                uh.y = split2(p2, p3, r2, r3);
                ul.x = packbf2(r0, r1);
                ul.y = packbf2(r2, r3);
                *(uint2*)(ah + v * 8) = uh;
                *(uint2*)(al + v * 8) = ul;
            }
            if (c < 6) {
                const float4* gj4 = (const float4*)(g + (size_t)jcm * DIM + (c + 2) * 64 + bq);
#pragma unroll
                for (int v = 0; v < 4; v++) pgj[v] = gj4[v];
            }
        }
        // mma chunk c: A from ping[c&1], B direct from L2
#pragma unroll
        for (int ks = 0; ks < 4; ks++) {
            const uint32_t ko = ks * 32;
            const unsigned char* pH = d_w1f_hi + (c * 4 + ks) * BSTEP + boff;
            const unsigned char* pL = d_w1f_lo + (c * 4 + ks) * BSTEP + boff;
            uint2 bh[5], bl[5];
#pragma unroll
            for (int nf = 0; nf < 5; nf++) {
                bh[nf] = *(const uint2*)(pH + nf * 256);
                bl[nf] = *(const uint2*)(pL + nf * 256);
            }
            uint32_t Ah0[4], Ah1[4], Al0[4], Al1[4];
            ldsm_x4(Ah0, aAddrH + pcur + ko);
            ldsm_x4(Ah1, aAddrH + pcur + 16 * RS1 + ko);
            ldsm_x4(Al0, aAddrL + pcur + ko);
            ldsm_x4(Al1, aAddrL + pcur + 16 * RS1 + ko);
            // term-major: same-accumulator dependency distance = 10
#pragma unroll
            for (int nf = 0; nf < 5; nf++) {
                mma16816(acc[0][nf], Ah0, bh[nf].x, bh[nf].y);
                mma16816(acc[1][nf], Ah1, bh[nf].x, bh[nf].y);
            }
#pragma unroll
            for (int nf = 0; nf < 5; nf++) {
                mma16816(acc[0][nf], Al0, bh[nf].x, bh[nf].y);
                mma16816(acc[1][nf], Al1, bh[nf].x, bh[nf].y);
            }
#pragma unroll
            for (int nf = 0; nf < 5; nf++) {
                mma16816(acc[0][nf], Ah0, bl[nf].x, bl[nf].y);
                mma16816(acc[1][nf], Ah1, bl[nf].x, bl[nf].y);
            }
        }
        __syncthreads();   // mma(c) done everywhere before ping[c&1] rebuild next iter
    }

    // ---- layer-1 epilogue: h1 = relu(acc + gia + gjt), gjt direct from L2 ----
#pragma unroll
    for (int mf = 0; mf < 2; mf++) {
        const int r = rowA + mf * 16;
        const float* gjr0 = d_gjt + jrow[r] * 152;
        const float* gjr8 = d_gjt + jrow[r + 8] * 152;
#pragma unroll
        for (int nf = 0; nf < 5; nf++) {
            const int n0 = wn * 40 + nf * 8 + tig * 2;
            if (n0 < HID) {
                const float2 ga = *(const float2*)(gias + n0);
                const float2 gj0 = *(const float2*)(gjr0 + n0);
                const float2 gj1 = *(const float2*)(gjr8 + n0);
                acc[mf][nf][0] = fmaxf(acc[mf][nf][0] + gj0.x + ga.x, 0.f);
                acc[mf][nf][1] = fmaxf(acc[mf][nf][1] + gj0.y + ga.y, 0.f);
                acc[mf][nf][2] = fmaxf(acc[mf][nf][2] + gj1.x + ga.x, 0.f);
                acc[mf][nf][3] = fmaxf(acc[mf][nf][3] + gj1.y + ga.y, 0.f);
            } else {
                acc[mf][nf][0] = acc[mf][nf][1] = acc[mf][nf][2] = acc[mf][nf][3] = 0.f;
            }
        }
    }

    // ---- write h1 split tiles into A2 (region free: layer-1 mma all done) ----
#pragma unroll
    for (int mf = 0; mf < 2; mf++) {
        const int r = rowA + mf * 16;
#pragma unroll
        for (int nf = 0; nf < 5; nf++) {
            const int n0 = wn * 40 + nf * 8 + tig * 2;
            float r0, r1;
            uint32_t h = split2(acc[mf][nf][0], acc[mf][nf][1], r0, r1);
            *(uint32_t*)(smem + OFF_A2_HI + r * RS2 + n0 * 2) = h;
            *(uint32_t*)(smem + OFF_A2_LO + r * RS2 + n0 * 2) = packbf2(r0, r1);
            h = split2(acc[mf][nf][2], acc[mf][nf][3], r0, r1);
            *(uint32_t*)(smem + OFF_A2_HI + (r + 8) * RS2 + n0 * 2) = h;
            *(uint32_t*)(smem + OFF_A2_LO + (r + 8) * RS2 + n0 * 2) = packbf2(r0, r1);
        }
    }

#pragma unroll
    for (int a = 0; a < 2; a++)
#pragma unroll
        for (int b = 0; b < 5; b++)
#pragma unroll
            for (int e = 0; e < 4; e++) acc[a][b][e] = 0.f;

    __syncthreads();   // A2 visible to all warps

    // ================= layer 2: K=160, 10 flat k16 steps, sync-free =================
    for (int s2 = 0; s2 < 10; s2++) {
        const uint32_t ko2 = s2 * 32;
        const unsigned char* pH = d_w2f_hi + s2 * BSTEP + boff;
        const unsigned char* pL = d_w2f_lo + s2 * BSTEP + boff;
        uint2 bh[5], bl[5];
#pragma unroll
        for (int nf = 0; nf < 5; nf++) {
            bh[nf] = *(const uint2*)(pH + nf * 256);
            bl[nf] = *(const uint2*)(pL + nf * 256);
        }
        uint32_t Ah0[4], Ah1[4], Al0[4], Al1[4];
        ldsm_x4(Ah0, a2AddrH + ko2);
        ldsm_x4(Ah1, a2AddrH + 16 * RS2 + ko2);
        ldsm_x4(Al0, a2AddrL + ko2);
        ldsm_x4(Al1, a2AddrL + 16 * RS2 + ko2);
#pragma unroll
        for (int nf = 0; nf < 5; nf++) {
            mma16816(acc[0][nf], Ah0, bh[nf].x, bh[nf].y);
            mma16816(acc[1][nf], Ah1, bh[nf].x, bh[nf].y);
        }
#pragma unroll
        for (int nf = 0; nf < 5; nf++) {
            mma16816(acc[0][nf], Al0, bh[nf].x, bh[nf].y);
            mma16816(acc[1][nf], Al1, bh[nf].x, bh[nf].y);
        }
#pragma unroll
        for (int nf = 0; nf < 5; nf++) {
            mma16816(acc[0][nf], Ah0, bl[nf].x, bl[nf].y);
            mma16816(acc[1][nf], Ah1, bl[nf].x, bl[nf].y);
        }
    }

    // ---- final: s = relu(acc2 + b2) . W3, quad-shuffle reduce ----
#pragma unroll
    for (int mf = 0; mf < 2; mf++) {
        float pr = 0.f, pr8 = 0.f;
#pragma unroll
        for (int nf = 0; nf < 5; nf++) {
            const int n0 = wn * 40 + nf * 8 + tig * 2;
            const float2 bb = *(const float2*)(b2s + n0);
            const float2 ww = *(const float2*)(w3s + n0);
            pr  += fmaxf(acc[mf][nf][0] + bb.x, 0.f) * ww.x
                 + fmaxf(acc[mf][nf][1] + bb.y, 0.f) * ww.y;
            pr8 += fmaxf(acc[mf][nf][2] + bb.x, 0.f) * ww.x
                 + fmaxf(acc[mf][nf][3] + bb.y, 0.f) * ww.y;
        }
        pr  += __shfl_xor_sync(0xffffffffu, pr, 1);
        pr  += __shfl_xor_sync(0xffffffffu, pr, 2);
        pr8 += __shfl_xor_sync(0xffffffffu, pr8, 1);
        pr8 += __shfl_xor_sync(0xffffffffu, pr8, 2);
        if (tig == 0) {
            sred[wn * MTILE + rowA + mf * 16]     = pr;
            sred[wn * MTILE + rowA + mf * 16 + 8] = pr8;
        }
    }
    __syncthreads();

    if (tid < MTILE) {
        const float s = sred[tid] + sred[MTILE + tid] + sred[2 * MTILE + tid] + sred[3 * MTILE + tid];
        const int k = k0 + tid;
        if (k < WIN) {
            const int j = i - WIN + k;
            out[i * OUTW + k] = (j >= 0) ? (sm[i] + smjf[tid] + s + b3[0]) : 0.f;
        } else if (k == WIN) {
            out[i * OUTW + k] = 0.f;  // trailing epsilon column
        }
    }
}

// ---------------------------------------------------------------------------
extern "C" void kernel_launch(void* const* d_in, const int* in_sizes, int n_in,
                              void* d_out, int out_size) {
    const float* g  = (const float*)d_in[0];
    const float* sm = (const float*)d_in[1];
    const float* W1 = (const float*)d_in[2];
    const float* b1 = (const float*)d_in[3];
    const float* W2 = (const float*)d_in[4];
    const float* b2 = (const float*)d_in[5];
    const float* W3 = (const float*)d_in[6];
    const float* b3 = (const float*)d_in[7];
    float* out = (float*)d_out;

    cudaFuncSetAttribute(pair_mma_kernel, cudaFuncAttributeMaxDynamicSharedMemorySize,
                         SMEM_TOTAL);

    // 128 GEMM blocks + 105 fragment-packing blocks
    prep_kernel<<<128 + 105, 256>>>(g, W1, b1, W2);
    pair_mma_kernel<<<dim3(4, N_SPANS), NTHREADS, SMEM_TOTAL>>>(g, sm, b2, W3, b3, out);
}

// round 16
// speedup vs baseline: 1.6070x; 1.2660x over previous
#include <cuda_runtime.h>
#include <cuda_fp16.h>
#include <stdint.h>

// ---------------- problem constants ----------------
#define N_SPANS 1024
#define DIM     512
#define HID     150
#define WIN     250
#define OUTW    (WIN + 1)
#define HPAD    160
#define NTHREADS 256
#define MTILE   64

// row strides (bytes) for fp16 A tiles (multiples of 16 for ldmatrix)
#define RS1 144        // layer-1 A: 64 fp16 + pad
#define RS2 336        // layer-2 A (h1): 160 fp16 + pad

// fragment-direct B: per k16-step: 160 n x 4 klane x 8 bytes = 5120 B
#define BSTEP 5120
#define NW1REC (32 * HPAD * 4)      // 20480 records, layer-1 (K=512 -> 32 steps)
#define NW2REC (10 * HPAD * 4)      // 6400 records,  layer-2 (K=160 -> 10 steps)

// ---------------- smem layout (bytes) ----------------
#define OFF_JROW 0                  // 64 ints
#define OFF_SMJ  256                // 64 floats
#define OFF_GIS  512                // 512 floats
#define OFF_GIAS 2560               // 160 floats
#define OFF_B2S  3200               // 160 floats
#define OFF_W3S  3840               // 160 floats
#define OFF_SRED 4480               // 4 x 64 floats -> ends 5504
#define OFF_A0_HI 5504              // 64 x RS1
#define OFF_A0_LO (OFF_A0_HI + MTILE*RS1)
#define OFF_A2_HI (OFF_A0_LO + MTILE*RS1)      // 64 x RS2 (also hosts A ping1)
#define OFF_A2_LO (OFF_A2_HI + MTILE*RS2)
#define SMEM_TOTAL (OFF_A2_LO + MTILE*RS2)     // 66944 -> 2 CTAs/SM
#define APING (OFF_A2_HI - OFF_A0_HI)          // ping1 aliases A2 region (time-separated)

// ---------------- device scratch ----------------
__device__ float d_gia[N_SPANS * HID];          // g@W1a + b1
__device__ float d_gjt[N_SPANS * 152];          // g@W1b, padded rows
// fragment-direct fp16 weights (single plane)
__device__ unsigned char d_w1f[NW1REC * 8];
__device__ unsigned char d_w2f[NW2REC * 8];

// ---------------- helpers ----------------
__device__ __forceinline__ uint32_t smem_u32(const void* p) {
    uint32_t a;
    asm("{ .reg .u64 t; cvta.to.shared.u64 t, %1; cvt.u32.u64 %0, t; }" : "=r"(a) : "l"(p));
    return a;
}
__device__ __forceinline__ uint32_t packh2(float a, float b) {
    __half2 t = __floats2half2_rn(a, b);
    return *reinterpret_cast<uint32_t*>(&t);
}
// fp16 split pair: returns hi half2, computes fp32 residuals
__device__ __forceinline__ uint32_t splith2(float a, float b, float& ra, float& rb) {
    __half ha = __float2half_rn(a), hb = __float2half_rn(b);
    ra = a - __half2float(ha);
    rb = b - __half2float(hb);
    __half2 t; t.x = ha; t.y = hb;
    return *reinterpret_cast<uint32_t*>(&t);
}
__device__ __forceinline__ void mma16816(float* c, const uint32_t* a,
                                         uint32_t b0, uint32_t b1) {
    asm volatile(
        "mma.sync.aligned.m16n8k16.row.col.f32.f16.f16.f32 "
        "{%0,%1,%2,%3}, {%4,%5,%6,%7}, {%8,%9}, {%0,%1,%2,%3};"
        : "+f"(c[0]), "+f"(c[1]), "+f"(c[2]), "+f"(c[3])
        : "r"(a[0]), "r"(a[1]), "r"(a[2]), "r"(a[3]), "r"(b0), "r"(b1));
}
__device__ __forceinline__ void ldsm_x4(uint32_t* r, uint32_t addr) {
    asm volatile("ldmatrix.sync.aligned.m8n8.x4.shared.b16 {%0,%1,%2,%3}, [%4];"
        : "=r"(r[0]), "=r"(r[1]), "=r"(r[2]), "=r"(r[3]) : "r"(addr));
}

// ---------------------------------------------------------------------------
// prep_kernel: blocks [0,128) = gia/gjt GEMM; blocks >=128 = fragment-direct
// fp16 weight packing. Record (s, n, klane) holds {W[k0][n], W[k0+1][n],
// W[k0+8][n], W[k0+9][n]} as fp16, k0 = s*16 + klane*2 — exactly the
// m16n8k16 col-major B fragment for lane: klane = lane&3, n' = lane>>2.
// ---------------------------------------------------------------------------
__global__ __launch_bounds__(256)
void prep_kernel(const float* __restrict__ g,
                 const float* __restrict__ W1,
                 const float* __restrict__ b1,
                 const float* __restrict__ W2) {
    const int tid = threadIdx.x;
    if (blockIdx.x < 128) {
        __shared__ float gs[32][64];
        __shared__ float Ws[64][80];
        const int mt = blockIdx.x >> 2, ct = blockIdx.x & 3;
        const int half = ct >> 1, ncol = (ct & 1) * 80;
        const int tx = tid & 15, ty = tid >> 4;

        float acc[2][5];
#pragma unroll
        for (int a = 0; a < 2; a++)
#pragma unroll
            for (int j = 0; j < 5; j++) acc[a][j] = 0.f;

        for (int kc = 0; kc < 8; kc++) {
#pragma unroll
            for (int r = 0; r < 8; r++) {
                const int ix = tid + r * 256, rr = ix >> 6, kk = ix & 63;
                gs[rr][kk] = g[(size_t)(mt * 32 + rr) * DIM + kc * 64 + kk];
            }
#pragma unroll
            for (int r = 0; r < 20; r++) {
                const int ix = tid + r * 256, kk = ix / 80, nn = ix % 80;
                const int col = ncol + nn;
                Ws[kk][nn] = (col < HID)
                    ? W1[(size_t)(half * DIM + kc * 64 + kk) * HID + col] : 0.f;
            }
            __syncthreads();
#pragma unroll 4
            for (int k = 0; k < 64; k++) {
                const float a0 = gs[ty * 2][k], a1 = gs[ty * 2 + 1][k];
#pragma unroll
                for (int j = 0; j < 5; j++) {
                    const float w = Ws[k][tx + 16 * j];
                    acc[0][j] += a0 * w;
                    acc[1][j] += a1 * w;
                }
            }
            __syncthreads();
        }
#pragma unroll
        for (int rr = 0; rr < 2; rr++) {
            const int row = mt * 32 + ty * 2 + rr;
#pragma unroll
            for (int j = 0; j < 5; j++) {
                const int col = ncol + tx + 16 * j;
                if (col < HID) {
                    if (!half) d_gia[row * HID + col] = acc[rr][j] + b1[col];
                    else       d_gjt[row * 152 + col] = acc[rr][j];
                }
            }
        }
        if (ct == 3 && tid < 64)
            d_gjt[(mt * 32 + (tid >> 1)) * 152 + HID + (tid & 1)] = 0.f;
        return;
    }

    // ---- fragment-direct fp16 weight packing (single plane) ----
    const int idx = (blockIdx.x - 128) * 256 + tid;
    float v[4];
    if (idx < NW1REC) {
        const int s = idx / (HPAD * 4), r = idx % (HPAD * 4), n = r >> 2, kl = r & 3;
        const int k0 = s * 16 + kl * 2;
#pragma unroll
        for (int e = 0; e < 4; e++) {
            const int k = k0 + (e >> 1) * 8 + (e & 1);
            v[e] = (n < HID) ? W1[(size_t)(2 * DIM + k) * HID + n] : 0.f;
        }
        uint2 uh;
        uh.x = packh2(v[0], v[1]);
        uh.y = packh2(v[2], v[3]);
        ((uint2*)d_w1f)[idx] = uh;
    } else if (idx < NW1REC + NW2REC) {
        const int i2 = idx - NW1REC;
        const int s = i2 / (HPAD * 4), r = i2 % (HPAD * 4), n = r >> 2, kl = r & 3;
        const int k0 = s * 16 + kl * 2;
#pragma unroll
        for (int e = 0; e < 4; e++) {
            const int k = k0 + (e >> 1) * 8 + (e & 1);
            v[e] = (n < HID && k < HID) ? W2[(size_t)k * HID + n] : 0.f;
        }
        uint2 uh;
        uh.x = packh2(v[0], v[1]);
        uh.y = packh2(v[2], v[3]);
        ((uint2*)d_w2f)[i2] = uh;
    }
}

// ---------------------------------------------------------------------------
// Main pair MLP. CTA = (span i, 64 window rows), 256 threads, 8 warps 2Mx4N,
// 2 CTAs/SM. fp16 2-term scheme: A = Ah + Al (fp16 split), B single fp16.
// B direct LDG of fragment-direct records (L2-resident). A ping-pongs.
// ---------------------------------------------------------------------------
__global__ __launch_bounds__(NTHREADS, 2)
void pair_mma_kernel(const float* __restrict__ g,
                     const float* __restrict__ sm,
                     const float* __restrict__ b2,
                     const float* __restrict__ W3,
                     const float* __restrict__ b3,
                     float* __restrict__ out) {
    extern __shared__ unsigned char smem[];
    const uint32_t sbase = smem_u32(smem);
    const int tid  = threadIdx.x;
    const int wid  = tid >> 5, lane = tid & 31;
    const int g8   = lane >> 2, tig = lane & 3;
    const int wm   = wid & 1, wn = wid >> 1;
    const int i    = blockIdx.y;
    const int k0   = blockIdx.x * MTILE;

    int*   jrow = (int*)(smem + OFF_JROW);
    float* smjf = (float*)(smem + OFF_SMJ);
    float* gis  = (float*)(smem + OFF_GIS);
    float* gias = (float*)(smem + OFF_GIAS);
    float* b2s  = (float*)(smem + OFF_B2S);
    float* w3s  = (float*)(smem + OFF_W3S);
    float* sred = (float*)(smem + OFF_SRED);

    // ---- init ----
    gis[tid] = g[(size_t)i * DIM + tid];
    gis[tid + 256] = g[(size_t)i * DIM + tid + 256];
    if (tid < HPAD) {
        const bool v = tid < HID;
        gias[tid] = v ? d_gia[i * HID + tid] : 0.f;
        b2s[tid]  = v ? b2[tid] : 0.f;
        w3s[tid]  = v ? W3[tid] : 0.f;
    }
    if (tid < MTILE) {
        const int k = k0 + tid;
        int j = i - WIN + k;
        int jc = j < 0 ? 0 : (j > N_SPANS - 1 ? N_SPANS - 1 : j);
        jrow[tid] = jc;
        smjf[tid] = sm[jc];
    }
    __syncthreads();

    float acc[2][5][4];
#pragma unroll
    for (int a = 0; a < 2; a++)
#pragma unroll
        for (int b = 0; b < 5; b++)
#pragma unroll
            for (int e = 0; e < 4; e++) acc[a][b][e] = 0.f;

    const int bm  = tid >> 2;           // build row (0..63)
    const int bq  = (tid & 3) * 16;     // build k-offset (floats)
    const int jcm = jrow[bm];
    const int rowA = wm * 32 + g8;      // fragment base A row

    // ldmatrix lane addresses (ping 0 base)
    const uint32_t aAddrH  = sbase + OFF_A0_HI + (wm * 32 + (lane & 15)) * RS1 + ((lane >> 4) << 4);
    const uint32_t aAddrL  = aAddrH + (OFF_A0_LO - OFF_A0_HI);
    const uint32_t a2AddrH = sbase + OFF_A2_HI + (wm * 32 + (lane & 15)) * RS2 + ((lane >> 4) << 4);
    const uint32_t a2AddrL = a2AddrH + (OFF_A2_LO - OFF_A2_HI);

    // fragment-direct B lane offset
    const uint32_t boff = ((uint32_t)(wn * 40 + (lane >> 2)) * 4 + (lane & 3)) * 8;

    // prefetch gj chunk 0 (16 floats per thread)
    float4 pgj[4];
    {
        const float4* gj4 = (const float4*)(g + (size_t)jcm * DIM + bq);
#pragma unroll
        for (int v = 0; v < 4; v++) pgj[v] = gj4[v];
    }

    // ---- build A(0) into ping0, prefetch gj chunk 1 ----
    {
        const float4* gi4 = (const float4*)(gis + bq);
        unsigned char* ah = smem + OFF_A0_HI + bm * RS1 + bq * 2;
        unsigned char* al = smem + OFF_A0_LO + bm * RS1 + bq * 2;
#pragma unroll
        for (int v = 0; v < 4; v++) {
            const float4 a4 = pgj[v], i4 = gi4[v];
            float p0 = a4.x * i4.x, p1 = a4.y * i4.y;
            float p2 = a4.z * i4.z, p3 = a4.w * i4.w;
            float r0, r1, r2, r3;
            uint2 uh, ul;
            uh.x = splith2(p0, p1, r0, r1);
            uh.y = splith2(p2, p3, r2, r3);
            ul.x = packh2(r0, r1);
            ul.y = packh2(r2, r3);
            *(uint2*)(ah + v * 8) = uh;
            *(uint2*)(al + v * 8) = ul;
        }
        const float4* gj4 = (const float4*)(g + (size_t)jcm * DIM + 64 + bq);
#pragma unroll
        for (int v = 0; v < 4; v++) pgj[v] = gj4[v];
    }
    __syncthreads();

    // ================= layer 1: K=512, 8 chunks of 64 =================
    for (int c = 0; c < 8; c++) {
        const uint32_t pcur = (c & 1) ? APING : 0;
        // build A(c+1) into the other ping (overlaps other warps' mma below)
        if (c < 7) {
            const uint32_t pnxt = (c & 1) ? 0 : APING;
            const float4* gi4 = (const float4*)(gis + (c + 1) * 64 + bq);
            unsigned char* ah = smem + OFF_A0_HI + pnxt + bm * RS1 + bq * 2;
            unsigned char* al = smem + OFF_A0_LO + pnxt + bm * RS1 + bq * 2;
#pragma unroll
            for (int v = 0; v < 4; v++) {
                const float4 a4 = pgj[v], i4 = gi4[v];
                float p0 = a4.x * i4.x, p1 = a4.y * i4.y;
                float p2 = a4.z * i4.z, p3 = a4.w * i4.w;
                float r0, r1, r2, r3;
                uint2 uh, ul;
                uh.x = splith2(p0, p1, r0, r1);
                uh.y = splith2(p2, p3, r2, r3);
                ul.x = packh2(r0, r1);
                ul.y = packh2(r2, r3);
                *(uint2*)(ah + v * 8) = uh;
                *(uint2*)(al + v * 8) = ul;
            }
            if (c < 6) {
                const float4* gj4 = (const float4*)(g + (size_t)jcm * DIM + (c + 2) * 64 + bq);
#pragma unroll
                for (int v = 0; v < 4; v++) pgj[v] = gj4[v];
            }
        }
        // mma chunk c: A from ping[c&1], B direct from L2 (single fp16 plane)
#pragma unroll
        for (int ks = 0; ks < 4; ks++) {
            const uint32_t ko = ks * 32;
            const unsigned char* pH = d_w1f + (c * 4 + ks) * BSTEP + boff;
            uint2 bh[5];
#pragma unroll
            for (int nf = 0; nf < 5; nf++)
                bh[nf] = *(const uint2*)(pH + nf * 256);
            uint32_t Ah0[4], Ah1[4], Al0[4], Al1[4];
            ldsm_x4(Ah0, aAddrH + pcur + ko);
            ldsm_x4(Ah1, aAddrH + pcur + 16 * RS1 + ko);
            ldsm_x4(Al0, aAddrL + pcur + ko);
            ldsm_x4(Al1, aAddrL + pcur + 16 * RS1 + ko);
            // term-major: same-accumulator dependency distance = 10
#pragma unroll
            for (int nf = 0; nf < 5; nf++) {
                mma16816(acc[0][nf], Ah0, bh[nf].x, bh[nf].y);
                mma16816(acc[1][nf], Ah1, bh[nf].x, bh[nf].y);
            }
#pragma unroll
            for (int nf = 0; nf < 5; nf++) {
                mma16816(acc[0][nf], Al0, bh[nf].x, bh[nf].y);
                mma16816(acc[1][nf], Al1, bh[nf].x, bh[nf].y);
            }
        }
        __syncthreads();   // mma(c) done everywhere before ping[c&1] rebuild next iter
    }

    // ---- layer-1 epilogue: h1 = relu(acc + gia + gjt), gjt direct from L2 ----
#pragma unroll
    for (int mf = 0; mf < 2; mf++) {
        const int r = rowA + mf * 16;
        const float* gjr0 = d_gjt + jrow[r] * 152;
        const float* gjr8 = d_gjt + jrow[r + 8] * 152;
#pragma unroll
        for (int nf = 0; nf < 5; nf++) {
            const int n0 = wn * 40 + nf * 8 + tig * 2;
            if (n0 < HID) {
                const float2 ga = *(const float2*)(gias + n0);
                const float2 gj0 = *(const float2*)(gjr0 + n0);
                const float2 gj1 = *(const float2*)(gjr8 + n0);
                acc[mf][nf][0] = fmaxf(acc[mf][nf][0] + gj0.x + ga.x, 0.f);
                acc[mf][nf][1] = fmaxf(acc[mf][nf][1] + gj0.y + ga.y, 0.f);
                acc[mf][nf][2] = fmaxf(acc[mf][nf][2] + gj1.x + ga.x, 0.f);
                acc[mf][nf][3] = fmaxf(acc[mf][nf][3] + gj1.y + ga.y, 0.f);
            } else {
                acc[mf][nf][0] = acc[mf][nf][1] = acc[mf][nf][2] = acc[mf][nf][3] = 0.f;
            }
        }
    }

    // ---- write h1 split tiles into A2 (region free: layer-1 mma all done) ----
#pragma unroll
    for (int mf = 0; mf < 2; mf++) {
        const int r = rowA + mf * 16;
#pragma unroll
        for (int nf = 0; nf < 5; nf++) {
            const int n0 = wn * 40 + nf * 8 + tig * 2;
            float r0, r1;
            uint32_t h = splith2(acc[mf][nf][0], acc[mf][nf][1], r0, r1);
            *(uint32_t*)(smem + OFF_A2_HI + r * RS2 + n0 * 2) = h;
            *(uint32_t*)(smem + OFF_A2_LO + r * RS2 + n0 * 2) = packh2(r0, r1);
            h = splith2(acc[mf][nf][2], acc[mf][nf][3], r0, r1);
            *(uint32_t*)(smem + OFF_A2_HI + (r + 8) * RS2 + n0 * 2) = h;
            *(uint32_t*)(smem + OFF_A2_LO + (r + 8) * RS2 + n0 * 2) = packh2(r0, r1);
        }
    }

#pragma unroll
    for (int a = 0; a < 2; a++)
#pragma unroll
        for (int b = 0; b < 5; b++)
#pragma unroll
            for (int e = 0; e < 4; e++) acc[a][b][e] = 0.f;

    __syncthreads();   // A2 visible to all warps

    // ================= layer 2: K=160, 10 flat k16 steps, sync-free =================
    for (int s2 = 0; s2 < 10; s2++) {
        const uint32_t ko2 = s2 * 32;
        const unsigned char* pH = d_w2f + s2 * BSTEP + boff;
        uint2 bh[5];
#pragma unroll
        for (int nf = 0; nf < 5; nf++)
            bh[nf] = *(const uint2*)(pH + nf * 256);
        uint32_t Ah0[4], Ah1[4], Al0[4], Al1[4];
        ldsm_x4(Ah0, a2AddrH + ko2);
        ldsm_x4(Ah1, a2AddrH + 16 * RS2 + ko2);
        ldsm_x4(Al0, a2AddrL + ko2);
        ldsm_x4(Al1, a2AddrL + 16 * RS2 + ko2);
#pragma unroll
        for (int nf = 0; nf < 5; nf++) {
            mma16816(acc[0][nf], Ah0, bh[nf].x, bh[nf].y);
            mma16816(acc[1][nf], Ah1, bh[nf].x, bh[nf].y);
        }
#pragma unroll
        for (int nf = 0; nf < 5; nf++) {
            mma16816(acc[0][nf], Al0, bh[nf].x, bh[nf].y);
            mma16816(acc[1][nf], Al1, bh[nf].x, bh[nf].y);
        }
    }

    // ---- final: s = relu(acc2 + b2) . W3, quad-shuffle reduce ----
#pragma unroll
    for (int mf = 0; mf < 2; mf++) {
        float pr = 0.f, pr8 = 0.f;
#pragma unroll
        for (int nf = 0; nf < 5; nf++) {
            const int n0 = wn * 40 + nf * 8 + tig * 2;
            const float2 bb = *(const float2*)(b2s + n0);
            const float2 ww = *(const float2*)(w3s + n0);
            pr  += fmaxf(acc[mf][nf][0] + bb.x, 0.f) * ww.x
                 + fmaxf(acc[mf][nf][1] + bb.y, 0.f) * ww.y;
            pr8 += fmaxf(acc[mf][nf][2] + bb.x, 0.f) * ww.x
                 + fmaxf(acc[mf][nf][3] + bb.y, 0.f) * ww.y;
        }
        pr  += __shfl_xor_sync(0xffffffffu, pr, 1);
        pr  += __shfl_xor_sync(0xffffffffu, pr, 2);
        pr8 += __shfl_xor_sync(0xffffffffu, pr8, 1);
        pr8 += __shfl_xor_sync(0xffffffffu, pr8, 2);
        if (tig == 0) {
            sred[wn * MTILE + rowA + mf * 16]     = pr;
            sred[wn * MTILE + rowA + mf * 16 + 8] = pr8;
        }
    }
    __syncthreads();

    if (tid < MTILE) {
        const float s = sred[tid] + sred[MTILE + tid] + sred[2 * MTILE + tid] + sred[3 * MTILE + tid];
        const int k = k0 + tid;
        if (k < WIN) {
            const int j = i - WIN + k;
            out[i * OUTW + k] = (j >= 0) ? (sm[i] + smjf[tid] + s + b3[0]) : 0.f;
        } else if (k == WIN) {
            out[i * OUTW + k] = 0.f;  // trailing epsilon column
        }
    }
}

// ---------------------------------------------------------------------------
extern "C" void kernel_launch(void* const* d_in, const int* in_sizes, int n_in,
                              void* d_out, int out_size) {
    const float* g  = (const float*)d_in[0];
    const float* sm = (const float*)d_in[1];
    const float* W1 = (const float*)d_in[2];
    const float* b1 = (const float*)d_in[3];
    const float* W2 = (const float*)d_in[4];
    const float* b2 = (const float*)d_in[5];
    const float* W3 = (const float*)d_in[6];
    const float* b3 = (const float*)d_in[7];
    float* out = (float*)d_out;

    cudaFuncSetAttribute(pair_mma_kernel, cudaFuncAttributeMaxDynamicSharedMemorySize,
                         SMEM_TOTAL);

    // 128 GEMM blocks + 105 fragment-packing blocks
    prep_kernel<<<128 + 105, 256>>>(g, W1, b1, W2);
    pair_mma_kernel<<<dim3(4, N_SPANS), NTHREADS, SMEM_TOTAL>>>(g, sm, b2, W3, b3, out);
}